// round 3
// baseline (speedup 1.0000x reference)
#include <cuda_runtime.h>
#include <cuda_fp16.h>
#include <cstdint>

#define FDIM     512
#define MTILE    128
#define NTHREADS 256

// Q converted to fp16, same [k][n] layout (row-major k, n contiguous).
// This is exactly the "col-major B" layout ldmatrix.trans wants for mma.row.col.
__device__ __half g_Qh[FDIM * FDIM];

// ---------------- smem layout ----------------
// A tile: 128 rows x 512 halves (1024B pitch, 64 chunks of 16B, XOR-swizzled) = 128KB
// B bufs: 2 x (64 rows x 128 halves = 256B pitch, 16 chunks, XOR-swizzled) = 32KB
// partial: 128 floats
#define SMEM_A    0
#define SMEM_B    131072
#define SMEM_PART 163840
#define SMEM_TOTAL (163840 + 512)

__device__ __forceinline__ uint32_t smem_u32(const void* p) {
    uint32_t a;
    asm("{ .reg .u64 t; cvta.to.shared.u64 t, %1; cvt.u32.u64 %0, t; }" : "=r"(a) : "l"(p));
    return a;
}

__device__ __forceinline__ void ldsm_x4(uint32_t* r, uint32_t addr) {
    asm volatile("ldmatrix.sync.aligned.m8n8.x4.shared.b16 {%0,%1,%2,%3}, [%4];"
                 : "=r"(r[0]), "=r"(r[1]), "=r"(r[2]), "=r"(r[3]) : "r"(addr));
}
__device__ __forceinline__ void ldsm_x4_trans(uint32_t* r, uint32_t addr) {
    asm volatile("ldmatrix.sync.aligned.m8n8.x4.trans.shared.b16 {%0,%1,%2,%3}, [%4];"
                 : "=r"(r[0]), "=r"(r[1]), "=r"(r[2]), "=r"(r[3]) : "r"(addr));
}
__device__ __forceinline__ void mma_16816(float* d, const uint32_t* a, uint32_t b0, uint32_t b1) {
    asm volatile(
        "mma.sync.aligned.m16n8k16.row.col.f32.f16.f16.f32 "
        "{%0,%1,%2,%3}, {%4,%5,%6,%7}, {%8,%9}, {%0,%1,%2,%3};"
        : "+f"(d[0]), "+f"(d[1]), "+f"(d[2]), "+f"(d[3])
        : "r"(a[0]), "r"(a[1]), "r"(a[2]), "r"(a[3]), "r"(b0), "r"(b1));
}
__device__ __forceinline__ void cp_async16(uint32_t saddr, const void* gaddr) {
    asm volatile("cp.async.cg.shared.global [%0], [%1], 16;" :: "r"(saddr), "l"(gaddr));
}

__device__ __forceinline__ uint32_t pack_h2(float lo, float hi) {
    uint32_t p;
    asm("cvt.rn.f16x2.f32 %0, %1, %2;" : "=r"(p) : "f"(hi), "f"(lo));
    return p;
}

// ---------------- Q fp32 -> fp16 convert (no transpose) ----------------
__global__ void convert_q_kernel(const float* __restrict__ Q) {
    int i = blockIdx.x * blockDim.x + threadIdx.x;       // 65536 threads, 4 elems each
    float4 v = ((const float4*)Q)[i];
    uint32_t h0 = pack_h2(v.x, v.y);
    uint32_t h1 = pack_h2(v.z, v.w);
    ((uint32_t*)g_Qh)[i * 2 + 0] = h0;
    ((uint32_t*)g_Qh)[i * 2 + 1] = h1;
}

// ---------------- fused triangular GEMM + per-row bilinear dot ----------------
__global__ __launch_bounds__(NTHREADS, 1)
void bilinear_kernel(const float* __restrict__ x, float* __restrict__ out) {
    extern __shared__ char smem[];
    const uint32_t sbase = smem_u32(smem);
    const uint32_t a_base = sbase + SMEM_A;
    const uint32_t b_base = sbase + SMEM_B;
    float* partial = (float*)(smem + SMEM_PART);

    const int tid  = threadIdx.x;
    const int lane = tid & 31;
    const int wid  = tid >> 5;
    const int warp_m = wid & 3;   // m32 slab
    const int warp_n = wid >> 2;  // n64 half of the 128-wide n-block
    const size_t row0 = (size_t)blockIdx.x * MTILE;

    if (tid < MTILE) partial[tid] = 0.f;

    // ---- Load A tile: x[row0..+127, 0..511] fp32 -> fp16, swizzled ----
    // 128 rows x 64 chunks(16B) = 8192 items, 32 per thread.
    #pragma unroll 4
    for (int i = 0; i < 32; ++i) {
        int item = tid + i * NTHREADS;
        int row = item >> 6, c = item & 63;
        const float4* src = (const float4*)(x + (row0 + row) * FDIM + c * 8);
        float4 f0 = src[0];
        float4 f1 = src[1];
        uint4 h;
        h.x = pack_h2(f0.x, f0.y);
        h.y = pack_h2(f0.z, f0.w);
        h.z = pack_h2(f1.x, f1.y);
        h.w = pack_h2(f1.z, f1.w);
        *(uint4*)(smem + row * 1024 + ((c ^ (row & 7)) << 4)) = h;
    }
    __syncthreads();

    // ---- B chunk producer: Q[kc*64 .. +63][j*128 .. +127] fp16 via cp.async ----
    auto issue_b = [&](int j, int kc, int buf) {
        uint32_t dst = b_base + buf * 16384;
        const __half* gb = g_Qh + (size_t)kc * 64 * FDIM + j * 128;
        #pragma unroll
        for (int i = 0; i < 4; ++i) {
            int item = tid + i * NTHREADS;
            int r = item >> 4, cn = item & 15;
            cp_async16(dst + r * 256 + ((cn ^ (r & 7)) << 4), gb + r * FDIM + cn * 8);
        }
        asm volatile("cp.async.commit_group;" ::: "memory");
    };

    float acc[2][8][4];
    #pragma unroll
    for (int mt = 0; mt < 2; ++mt)
        #pragma unroll
        for (int nt = 0; nt < 8; ++nt)
            #pragma unroll
            for (int v = 0; v < 4; ++v) acc[mt][nt][v] = 0.f;

    issue_b(0, 0, 0);
    int cidx = 0;

    for (int j = 0; j < 4; ++j) {
        const int nch = 2 * (j + 1);                 // triangular: k only up to 128*(j+1)
        for (int kc = 0; kc < nch; ++kc, ++cidx) {
            const bool has_next = !(j == 3 && kc == nch - 1);
            if (has_next) {
                int nj  = (kc + 1 < nch) ? j : j + 1;
                int nkc = (kc + 1 < nch) ? kc + 1 : 0;
                issue_b(nj, nkc, (cidx + 1) & 1);
                asm volatile("cp.async.wait_group 1;" ::: "memory");
            } else {
                asm volatile("cp.async.wait_group 0;" ::: "memory");
            }
            __syncthreads();

            const uint32_t bbuf = b_base + (cidx & 1) * 16384;
            #pragma unroll
            for (int ks = 0; ks < 4; ++ks) {
                // A fragments: two m16 tiles of this warp's m32 slab
                uint32_t afr[2][4];
                #pragma unroll
                for (int mt = 0; mt < 2; ++mt) {
                    int rowm = warp_m * 32 + mt * 16 + (lane & 15);
                    int ck = kc * 8 + ks * 2 + (lane >> 4);     // 16B chunk within row
                    ldsm_x4(afr[mt], a_base + rowm * 1024 + ((ck ^ (rowm & 7)) << 4));
                }
                // B fragments: warp's n64 as 4 x (n16) ldmatrix.x4.trans
                uint32_t bfr[4][4];
                #pragma unroll
                for (int np = 0; np < 4; ++np) {
                    int krow = ks * 16 + (lane & 15);
                    int cn = warp_n * 8 + np * 2 + (lane >> 4);
                    ldsm_x4_trans(bfr[np], bbuf + krow * 256 + ((cn ^ (krow & 7)) << 4));
                }
                #pragma unroll
                for (int mt = 0; mt < 2; ++mt)
                    #pragma unroll
                    for (int nt = 0; nt < 8; ++nt)
                        mma_16816(acc[mt][nt], afr[mt],
                                  bfr[nt >> 1][(nt & 1) * 2], bfr[nt >> 1][(nt & 1) * 2 + 1]);
            }
            __syncthreads();
        }

        // ---- Epilogue for n-block j: out[m] += sum_n t[m,n] * x_fp32[m,n] ----
        #pragma unroll
        for (int mt = 0; mt < 2; ++mt) {
            #pragma unroll
            for (int h = 0; h < 2; ++h) {
                int m_loc = warp_m * 32 + mt * 16 + h * 8 + (lane >> 2);
                const float* xrow = x + (row0 + m_loc) * FDIM + j * 128 + warp_n * 64 + (lane & 3) * 2;
                float s = 0.f;
                #pragma unroll
                for (int nt = 0; nt < 8; ++nt) {
                    float2 xv = *(const float2*)(xrow + nt * 8);
                    s += acc[mt][nt][h * 2 + 0] * xv.x + acc[mt][nt][h * 2 + 1] * xv.y;
                }
                s += __shfl_xor_sync(0xFFFFFFFFu, s, 1);
                s += __shfl_xor_sync(0xFFFFFFFFu, s, 2);
                if ((lane & 3) == 0) atomicAdd(&partial[m_loc], s);
            }
        }
        // reset accumulators for next n-block
        #pragma unroll
        for (int mt = 0; mt < 2; ++mt)
            #pragma unroll
            for (int nt = 0; nt < 8; ++nt)
                #pragma unroll
                for (int v = 0; v < 4; ++v) acc[mt][nt][v] = 0.f;
    }

    __syncthreads();
    if (tid < MTILE) out[row0 + tid] = partial[tid];
}

// ---------------- launch ----------------
extern "C" void kernel_launch(void* const* d_in, const int* in_sizes, int n_in,
                              void* d_out, int out_size) {
    const float* x = (const float*)d_in[0];
    const float* Q = (const float*)d_in[1];
    if (n_in >= 2 && in_sizes[0] == FDIM * FDIM && in_sizes[1] != FDIM * FDIM) {
        const float* t = x; x = Q; Q = t;
    }
    float* out = (float*)d_out;

    cudaFuncSetAttribute(bilinear_kernel,
                         cudaFuncAttributeMaxDynamicSharedMemorySize, SMEM_TOTAL);

    convert_q_kernel<<<(FDIM * FDIM / 4) / 256, 256>>>(Q);
    bilinear_kernel<<<131072 / MTILE, NTHREADS, SMEM_TOTAL>>>(x, out);
}